// round 11
// baseline (speedup 1.0000x reference)
#include <cuda_runtime.h>
#include <cuda_bf16.h>
#include <cstdint>

constexpr int NN  = 100000;   // nodes
constexpr int EE  = 1600000;  // edges
constexpr int GG  = 256;      // graphs
constexpr int DIN = 64;
constexpr int HID = 128;

// Scratch (device globals — no allocation allowed)
__device__ uint32_t g_aggHi[(size_t)NN * 64];   // packed bf16x2 hi plane (K<=128)
__device__ uint32_t g_aggLo[(size_t)NN * 64];   // packed bf16x2 lo plane
__device__ float g_h1 [(size_t)NN * HID];
__device__ float g_h2 [(size_t)NN * HID];
__device__ float g_gsum[GG];
__device__ float g_gcnt[GG];
// CSR scratch
__device__ int g_cnt [NN];
__device__ int g_off [NN];
__device__ int g_off2[NN];
__device__ int g_ssrc[EE];

// ===========================================================================
// Warp-level tensor-core primitives (base ISA: valid on target sm_100)
// ===========================================================================
__device__ __forceinline__ uint32_t smem_u32(const void* p) {
    uint32_t a;
    asm("{ .reg .u64 t; cvta.to.shared.u64 t, %1; cvt.u32.u64 %0, t; }" : "=r"(a) : "l"(p));
    return a;
}

__device__ __forceinline__ void ldmatrix_x4(uint32_t* r, uint32_t addr) {
    asm volatile("ldmatrix.sync.aligned.m8n8.x4.shared.b16 {%0,%1,%2,%3}, [%4];"
                 : "=r"(r[0]), "=r"(r[1]), "=r"(r[2]), "=r"(r[3]) : "r"(addr));
}
__device__ __forceinline__ void ldmatrix_x2(uint32_t* r, uint32_t addr) {
    asm volatile("ldmatrix.sync.aligned.m8n8.x2.shared.b16 {%0,%1}, [%2];"
                 : "=r"(r[0]), "=r"(r[1]) : "r"(addr));
}

// D(16x8,f32) += A(16x16,bf16,row) * B(16x8,bf16,col)
__device__ __forceinline__ void mma_16816(float* d, const uint32_t* a, const uint32_t* b) {
    asm volatile(
        "mma.sync.aligned.m16n8k16.row.col.f32.bf16.bf16.f32 "
        "{%0,%1,%2,%3}, {%4,%5,%6,%7}, {%8,%9}, {%0,%1,%2,%3};"
        : "+f"(d[0]), "+f"(d[1]), "+f"(d[2]), "+f"(d[3])
        : "r"(a[0]), "r"(a[1]), "r"(a[2]), "r"(a[3]), "r"(b[0]), "r"(b[1]));
}

// Split two floats into packed bf16x2 hi and lo words
__device__ __forceinline__ void split2(float x, float y, uint32_t& hp, uint32_t& lp) {
    __nv_bfloat16 hx = __float2bfloat16(x), hy = __float2bfloat16(y);
    __nv_bfloat16 lx = __float2bfloat16(x - __bfloat162float(hx));
    __nv_bfloat16 ly = __float2bfloat16(y - __bfloat162float(hy));
    hp = ((uint32_t)__bfloat16_as_ushort(hy) << 16) | __bfloat16_as_ushort(hx);
    lp = ((uint32_t)__bfloat16_as_ushort(ly) << 16) | __bfloat16_as_ushort(lx);
}

// ===========================================================================
// CSR build: zero -> histogram -> scan (emits two offset copies) -> reorder
// ===========================================================================
__global__ void zero_cnt() {
    int t = blockIdx.x * blockDim.x + threadIdx.x;
    if (t < NN) g_cnt[t] = 0;
}

__global__ void hist_kernel(const int* __restrict__ dst) {
    int e = blockIdx.x * blockDim.x + threadIdx.x;
    if (e < EE) atomicAdd(&g_cnt[__ldg(&dst[e])], 1);
}

constexpr int SCAN_T  = 1024;
constexpr int SCAN_CH = (NN + SCAN_T - 1) / SCAN_T;   // 98

__global__ void scan_kernel() {
    __shared__ int ssum[SCAN_T];
    int t = threadIdx.x;
    int base = t * SCAN_CH;
    int s = 0;
    #pragma unroll 4
    for (int i = 0; i < SCAN_CH; i++) {
        int j = base + i;
        if (j < NN) s += g_cnt[j];
    }
    ssum[t] = s;
    __syncthreads();
    for (int d = 1; d < SCAN_T; d <<= 1) {
        int v = (t >= d) ? ssum[t - d] : 0;
        __syncthreads();
        ssum[t] += v;
        __syncthreads();
    }
    int run = (t > 0) ? ssum[t - 1] : 0;
    for (int i = 0; i < SCAN_CH; i++) {
        int j = base + i;
        if (j < NN) { g_off[j] = run; g_off2[j] = run; run += g_cnt[j]; }
    }
}

__global__ void reorder_kernel(const int* __restrict__ src,
                               const int* __restrict__ dst) {
    int e = blockIdx.x * blockDim.x + threadIdx.x;
    if (e < EE) {
        int d = __ldg(&dst[e]);
        int slot = atomicAdd(&g_off2[d], 1);
        g_ssrc[slot] = __ldg(&src[e]);
    }
}

// ===========================================================================
// Gather aggregation -> bf16 hi/lo planes: agg[n] = x[n] + sum_{nbr} x[s]
// High-occupancy standalone kernels (one warp per node).
// ===========================================================================
__global__ void gather_split_64(const float* __restrict__ x) {
    int gw   = (blockIdx.x * blockDim.x + threadIdx.x) >> 5;
    int lane = threadIdx.x & 31;
    int nw   = (gridDim.x * blockDim.x) >> 5;
    for (int n = gw; n < NN; n += nw) {
        int lo = g_off[n], deg = g_cnt[n];
        float2 acc = __ldg((const float2*)(x + (size_t)n * 64) + lane);
        int i = 0;
        for (; i + 3 < deg; i += 4) {
            int s0 = __ldg(&g_ssrc[lo + i]);
            int s1 = __ldg(&g_ssrc[lo + i + 1]);
            int s2 = __ldg(&g_ssrc[lo + i + 2]);
            int s3 = __ldg(&g_ssrc[lo + i + 3]);
            float2 v0 = __ldg((const float2*)(x + (size_t)s0 * 64) + lane);
            float2 v1 = __ldg((const float2*)(x + (size_t)s1 * 64) + lane);
            float2 v2 = __ldg((const float2*)(x + (size_t)s2 * 64) + lane);
            float2 v3 = __ldg((const float2*)(x + (size_t)s3 * 64) + lane);
            acc.x += v0.x + v1.x + v2.x + v3.x;
            acc.y += v0.y + v1.y + v2.y + v3.y;
        }
        for (; i < deg; i++) {
            int s = __ldg(&g_ssrc[lo + i]);
            float2 v = __ldg((const float2*)(x + (size_t)s * 64) + lane);
            acc.x += v.x; acc.y += v.y;
        }
        uint32_t hp, lp;
        split2(acc.x, acc.y, hp, lp);
        g_aggHi[(size_t)n * 32 + lane] = hp;
        g_aggLo[(size_t)n * 32 + lane] = lp;
    }
}

__global__ void gather_split_128(const float* __restrict__ x) {
    int gw   = (blockIdx.x * blockDim.x + threadIdx.x) >> 5;
    int lane = threadIdx.x & 31;
    int nw   = (gridDim.x * blockDim.x) >> 5;
    for (int n = gw; n < NN; n += nw) {
        int lo = g_off[n], deg = g_cnt[n];
        float4 acc = __ldg((const float4*)(x + (size_t)n * 128) + lane);
        int i = 0;
        for (; i + 3 < deg; i += 4) {
            int s0 = __ldg(&g_ssrc[lo + i]);
            int s1 = __ldg(&g_ssrc[lo + i + 1]);
            int s2 = __ldg(&g_ssrc[lo + i + 2]);
            int s3 = __ldg(&g_ssrc[lo + i + 3]);
            float4 v0 = __ldg((const float4*)(x + (size_t)s0 * 128) + lane);
            float4 v1 = __ldg((const float4*)(x + (size_t)s1 * 128) + lane);
            float4 v2 = __ldg((const float4*)(x + (size_t)s2 * 128) + lane);
            float4 v3 = __ldg((const float4*)(x + (size_t)s3 * 128) + lane);
            acc.x += v0.x + v1.x + v2.x + v3.x;
            acc.y += v0.y + v1.y + v2.y + v3.y;
            acc.z += v0.z + v1.z + v2.z + v3.z;
            acc.w += v0.w + v1.w + v2.w + v3.w;
        }
        for (; i < deg; i++) {
            int s = __ldg(&g_ssrc[lo + i]);
            float4 v = __ldg((const float4*)(x + (size_t)s * 128) + lane);
            acc.x += v.x; acc.y += v.y; acc.z += v.z; acc.w += v.w;
        }
        uint2 hp, lp;
        split2(acc.x, acc.y, hp.x, lp.x);
        split2(acc.z, acc.w, hp.y, lp.y);
        *(uint2*)(g_aggHi + (size_t)n * 64 + lane * 2) = hp;
        *(uint2*)(g_aggLo + (size_t)n * 64 + lane * 2) = lp;
    }
}

// ===========================================================================
// Fused GEMM pair: out = relu(relu(A @ W1 + b1) @ W2 + b2)
// 512 threads: warp w owns output cols [8w, 8w+8) -> half the per-warp mma/
// ldmatrix/epilogue work of the 256-thread version, 2x warps per SM.
// A comes pre-split (hi/lo bf16 planes) from the gather kernel.
// ===========================================================================
template <int K>
__global__ __launch_bounds__(512, 1)
void fused_pair(const uint32_t* __restrict__ aggHi, const uint32_t* __restrict__ aggLo,
                const float* __restrict__ W1, const float* __restrict__ b1,
                const float* __restrict__ W2, const float* __restrict__ b2,
                float* __restrict__ out, int ntiles)
{
    constexpr int KCH1 = K / 16;         // k-chunks of GEMM1
    constexpr int RSB1 = K * 2 + 16;     // sA row stride bytes (conflict-free)
    constexpr int RSB2 = 128 * 2 + 16;   // sI row stride bytes
    constexpr int KW4  = K / 4;          // uint2 copies per row
    extern __shared__ __align__(16) char smem[];
    char* sAhi = smem;
    char* sAlo = smem + 128 * RSB1;
    char* sIhi = smem + 2 * 128 * RSB1;
    char* sIlo = sIhi + 128 * RSB2;

    const int tid  = threadIdx.x;
    const int wid  = tid >> 5;           // 0..15
    const int lane = tid & 31;
    const uint32_t uAhi = smem_u32(sAhi), uAlo = smem_u32(sAlo);
    const uint32_t uIhi = smem_u32(sIhi), uIlo = smem_u32(sIlo);

    // ---- Stage W1^T hi/lo into sI (temp), extract B1 fragments ----
    uint32_t B1hi[KCH1][2], B1lo[KCH1][2];
    for (int i = tid; i < K * 128; i += 512) {
        int k = i >> 7, n = i & 127;                  // W1[k][n], coalesced
        float w = __ldg(&W1[i]);
        __nv_bfloat16 hi = __float2bfloat16(w);
        __nv_bfloat16 lo = __float2bfloat16(w - __bfloat162float(hi));
        *(__nv_bfloat16*)(sIhi + n * RSB1 + k * 2) = hi;
        *(__nv_bfloat16*)(sIlo + n * RSB1 + k * 2) = lo;
    }
    __syncthreads();
    {
        int r = lane & 7, mat = (lane >> 3) & 1;
        int n = wid * 8 + r;                          // warp w: n-tile at 8w
        #pragma unroll
        for (int c = 0; c < KCH1; c++) {
            uint32_t off = (uint32_t)n * RSB1 + c * 32 + mat * 16;
            ldmatrix_x2(B1hi[c], uIhi + off);
            ldmatrix_x2(B1lo[c], uIlo + off);
        }
    }
    __syncthreads();

    // ---- Stage W2^T hi/lo into sI (temp), extract B2 fragments ----
    uint32_t B2hi[8][2], B2lo[8][2];
    for (int i = tid; i < 128 * 128; i += 512) {
        int k = i >> 7, n = i & 127;
        float w = __ldg(&W2[i]);
        __nv_bfloat16 hi = __float2bfloat16(w);
        __nv_bfloat16 lo = __float2bfloat16(w - __bfloat162float(hi));
        *(__nv_bfloat16*)(sIhi + n * RSB2 + k * 2) = hi;
        *(__nv_bfloat16*)(sIlo + n * RSB2 + k * 2) = lo;
    }
    __syncthreads();
    {
        int r = lane & 7, mat = (lane >> 3) & 1;
        int n = wid * 8 + r;
        #pragma unroll
        for (int c = 0; c < 8; c++) {
            uint32_t off = (uint32_t)n * RSB2 + c * 32 + mat * 16;
            ldmatrix_x2(B2hi[c], uIhi + off);
            ldmatrix_x2(B2lo[c], uIlo + off);
        }
    }
    __syncthreads();

    // Per-thread bias scalars (cols fixed for the whole kernel)
    const int c0 = wid * 8 + (lane & 3) * 2;
    const float b1s0 = __ldg(&b1[c0]), b1s1 = __ldg(&b1[c0 + 1]);
    const float b2s0 = __ldg(&b2[c0]), b2s1 = __ldg(&b2[c0 + 1]);

    // ldmatrix.x4 lane address pattern for A (row-major 16x16)
    const int ar = (lane & 7) + ((lane & 8) ? 8 : 0);
    const int ak = (lane & 16) ? 16 : 0;

    for (int tile = blockIdx.x; tile < ntiles; tile += gridDim.x) {
        const int base = tile * 128;

        // ---- 1) Copy pre-split A planes into smem (uint2 = 4 bf16) ----
        for (int i = tid; i < 128 * KW4; i += 512) {
            int row = i / KW4;
            int j   = i - row * KW4;          // uint2 index within row
            int n   = base + row;
            uint2 hp = make_uint2(0u, 0u), lp = make_uint2(0u, 0u);
            if (n < NN) {
                hp = __ldg((const uint2*)(aggHi + (size_t)n * (K / 2)) + j);
                lp = __ldg((const uint2*)(aggLo + (size_t)n * (K / 2)) + j);
            }
            *(uint2*)(sAhi + row * RSB1 + j * 8) = hp;
            *(uint2*)(sAlo + row * RSB1 + j * 8) = lp;
        }
        __syncthreads();

        // ---- 2) GEMM1 (m-tile pairs) -> relu -> split -> sI ----
        #pragma unroll
        for (int mp = 0; mp < 4; mp++) {
            float acc[2][4];
            #pragma unroll
            for (int t = 0; t < 2; t++)
                #pragma unroll
                for (int q = 0; q < 4; q++) acc[t][q] = 0.f;

            #pragma unroll
            for (int c = 0; c < KCH1; c++) {
                #pragma unroll
                for (int t = 0; t < 2; t++) {
                    uint32_t arow = (uint32_t)(mp * 32 + t * 16 + ar) * RSB1 + ak + c * 32;
                    uint32_t ahi[4], alo[4];
                    ldmatrix_x4(ahi, uAhi + arow);
                    ldmatrix_x4(alo, uAlo + arow);
                    mma_16816(acc[t], ahi, B1hi[c]);
                    mma_16816(acc[t], ahi, B1lo[c]);
                    mma_16816(acc[t], alo, B1hi[c]);
                }
            }
            #pragma unroll
            for (int t = 0; t < 2; t++) {
                int r0 = mp * 32 + t * 16 + (lane >> 2);
                int r1 = r0 + 8;
                float v0 = fmaxf(acc[t][0] + b1s0, 0.f);
                float v1 = fmaxf(acc[t][1] + b1s1, 0.f);
                float v2 = fmaxf(acc[t][2] + b1s0, 0.f);
                float v3 = fmaxf(acc[t][3] + b1s1, 0.f);
                uint32_t hp, lp;
                split2(v0, v1, hp, lp);
                *(uint32_t*)(sIhi + r0 * RSB2 + c0 * 2) = hp;
                *(uint32_t*)(sIlo + r0 * RSB2 + c0 * 2) = lp;
                split2(v2, v3, hp, lp);
                *(uint32_t*)(sIhi + r1 * RSB2 + c0 * 2) = hp;
                *(uint32_t*)(sIlo + r1 * RSB2 + c0 * 2) = lp;
            }
        }
        __syncthreads();

        // ---- 3) GEMM2 (m-tile pairs) -> bias+relu -> gmem ----
        #pragma unroll
        for (int mp = 0; mp < 4; mp++) {
            float acc[2][4];
            #pragma unroll
            for (int t = 0; t < 2; t++)
                #pragma unroll
                for (int q = 0; q < 4; q++) acc[t][q] = 0.f;

            #pragma unroll
            for (int c = 0; c < 8; c++) {
                #pragma unroll
                for (int t = 0; t < 2; t++) {
                    uint32_t arow = (uint32_t)(mp * 32 + t * 16 + ar) * RSB2 + ak + c * 32;
                    uint32_t ahi[4], alo[4];
                    ldmatrix_x4(ahi, uIhi + arow);
                    ldmatrix_x4(alo, uIlo + arow);
                    mma_16816(acc[t], ahi, B2hi[c]);
                    mma_16816(acc[t], ahi, B2lo[c]);
                    mma_16816(acc[t], alo, B2hi[c]);
                }
            }
            #pragma unroll
            for (int t = 0; t < 2; t++) {
                int r0 = base + mp * 32 + t * 16 + (lane >> 2);
                int r1 = r0 + 8;
                if (r0 < NN) {
                    float2 o;
                    o.x = fmaxf(acc[t][0] + b2s0, 0.f);
                    o.y = fmaxf(acc[t][1] + b2s1, 0.f);
                    *(float2*)(out + (size_t)r0 * 128 + c0) = o;
                }
                if (r1 < NN) {
                    float2 o;
                    o.x = fmaxf(acc[t][2] + b2s0, 0.f);
                    o.y = fmaxf(acc[t][3] + b2s1, 0.f);
                    *(float2*)(out + (size_t)r1 * 128 + c0) = o;
                }
            }
        }
        __syncthreads();   // sA/sI free before next tile
    }
}

// ===========================================================================
__global__ void zero_pool() {
    int t = threadIdx.x;
    if (t < GG) { g_gsum[t] = 0.f; g_gcnt[t] = 0.f; }
}

__global__ void pool_dot(const float* __restrict__ h,
                         const float* __restrict__ Wfc,
                         const int* __restrict__ batch) {
    __shared__ float sw[128];
    if (threadIdx.x < 128) sw[threadIdx.x] = Wfc[threadIdx.x];
    __syncthreads();
    int gw    = (blockIdx.x * blockDim.x + threadIdx.x) >> 5;
    int lane  = threadIdx.x & 31;
    int nwarp = (gridDim.x * blockDim.x) >> 5;
    for (int node = gw; node < NN; node += nwarp) {
        float4 v = ((const float4*)(h + (size_t)node * 128))[lane];
        float4 w = ((const float4*)sw)[lane];
        float p = v.x * w.x + v.y * w.y + v.z * w.z + v.w * w.w;
        #pragma unroll
        for (int o = 16; o > 0; o >>= 1) p += __shfl_down_sync(0xffffffffu, p, o);
        if (lane == 0) {
            int b = __ldg(&batch[node]);
            atomicAdd(&g_gsum[b], p);
            atomicAdd(&g_gcnt[b], 1.0f);
        }
    }
}

__global__ void finalize(float* __restrict__ out, const float* __restrict__ bfc) {
    int t = threadIdx.x;
    if (t < GG) out[t] = g_gsum[t] / fmaxf(g_gcnt[t], 1.0f) + bfc[0];
}

// ===========================================================================
extern "C" void kernel_launch(void* const* d_in, const int* in_sizes, int n_in,
                              void* d_out, int out_size) {
    const float* x     = (const float*)d_in[0];
    const int*   ei    = (const int*)d_in[1];     // int32
    const int*   batch = (const int*)d_in[2];     // int32
    const float* W1a = (const float*)d_in[3];
    const float* b1a = (const float*)d_in[4];
    const float* W1b = (const float*)d_in[5];
    const float* b1b = (const float*)d_in[6];
    const float* W2a = (const float*)d_in[7];
    const float* b2a = (const float*)d_in[8];
    const float* W2b = (const float*)d_in[9];
    const float* b2b = (const float*)d_in[10];
    const float* Wfc = (const float*)d_in[11];
    const float* bfc = (const float*)d_in[12];
    float* out = (float*)d_out;

    const int* esrc = ei;
    const int* edst = ei + EE;

    float *h1, *h2;
    uint32_t *aggHi, *aggLo;
    cudaGetSymbolAddress((void**)&h1, g_h1);
    cudaGetSymbolAddress((void**)&h2, g_h2);
    cudaGetSymbolAddress((void**)&aggHi, g_aggHi);
    cudaGetSymbolAddress((void**)&aggLo, g_aggLo);

    const int smemF64  = 2 * 128 * (64 * 2 + 16) + 2 * 128 * (128 * 2 + 16);   // 106,496
    const int smemF128 = 4 * 128 * (128 * 2 + 16);                             // 139,264
    cudaFuncSetAttribute(fused_pair<64>,  cudaFuncAttributeMaxDynamicSharedMemorySize, smemF64);
    cudaFuncSetAttribute(fused_pair<128>, cudaFuncAttributeMaxDynamicSharedMemorySize, smemF128);

    const int ntiles = (NN + 127) / 128;   // 782

    // ---- CSR build (per call; reused by both layers) ----
    zero_cnt<<<(NN + 255) / 256, 256>>>();
    hist_kernel<<<(EE + 255) / 256, 256>>>(edst);
    scan_kernel<<<1, SCAN_T>>>();
    reorder_kernel<<<(EE + 255) / 256, 256>>>(esrc, edst);

    // ---- Layer 1 ----
    gather_split_64<<<1024, 256>>>(x);
    fused_pair<64> <<<148, 512, smemF64 >>>(aggHi, aggLo, W1a, b1a, W1b, b1b, h1, ntiles);

    // ---- Layer 2 ----
    gather_split_128<<<1024, 256>>>(h1);
    fused_pair<128><<<148, 512, smemF128>>>(aggHi, aggLo, W2a, b2a, W2b, b2b, h2, ntiles);

    // ---- Pool + FC ----
    zero_pool<<<1, 256>>>();
    pool_dot<<<512, 256>>>(h2, Wfc, batch);
    finalize<<<1, 256>>>(out, bfc);
}

// round 12
// speedup vs baseline: 1.2243x; 1.2243x over previous
#include <cuda_runtime.h>
#include <cuda_bf16.h>
#include <cstdint>

constexpr int NN  = 100000;   // nodes
constexpr int EE  = 1600000;  // edges
constexpr int GG  = 256;      // graphs
constexpr int DIN = 64;
constexpr int HID = 128;

// Scratch (device globals — no allocation allowed)
__device__ uint32_t g_aggHi[(size_t)NN * 64];   // packed bf16x2 hi plane (K<=128)
__device__ uint32_t g_aggLo[(size_t)NN * 64];   // packed bf16x2 lo plane
__device__ float g_h1 [(size_t)NN * HID];
__device__ float g_gsum[GG];
// CSR scratch
__device__ int g_cnt [NN];
__device__ int g_off [NN];
__device__ int g_pos [EE];
__device__ int g_ssrc[EE];

// ===========================================================================
// Warp-level tensor-core primitives (base ISA: valid on target sm_100)
// ===========================================================================
__device__ __forceinline__ uint32_t smem_u32(const void* p) {
    uint32_t a;
    asm("{ .reg .u64 t; cvta.to.shared.u64 t, %1; cvt.u32.u64 %0, t; }" : "=r"(a) : "l"(p));
    return a;
}

__device__ __forceinline__ void ldmatrix_x4(uint32_t* r, uint32_t addr) {
    asm volatile("ldmatrix.sync.aligned.m8n8.x4.shared.b16 {%0,%1,%2,%3}, [%4];"
                 : "=r"(r[0]), "=r"(r[1]), "=r"(r[2]), "=r"(r[3]) : "r"(addr));
}
__device__ __forceinline__ void ldmatrix_x2(uint32_t* r, uint32_t addr) {
    asm volatile("ldmatrix.sync.aligned.m8n8.x2.shared.b16 {%0,%1}, [%2];"
                 : "=r"(r[0]), "=r"(r[1]) : "r"(addr));
}

// D(16x8,f32) += A(16x16,bf16,row) * B(16x8,bf16,col)
__device__ __forceinline__ void mma_16816(float* d, const uint32_t* a, const uint32_t* b) {
    asm volatile(
        "mma.sync.aligned.m16n8k16.row.col.f32.bf16.bf16.f32 "
        "{%0,%1,%2,%3}, {%4,%5,%6,%7}, {%8,%9}, {%0,%1,%2,%3};"
        : "+f"(d[0]), "+f"(d[1]), "+f"(d[2]), "+f"(d[3])
        : "r"(a[0]), "r"(a[1]), "r"(a[2]), "r"(a[3]), "r"(b[0]), "r"(b[1]));
}

// Split two floats into packed bf16x2 hi and lo words
__device__ __forceinline__ void split2(float x, float y, uint32_t& hp, uint32_t& lp) {
    __nv_bfloat16 hx = __float2bfloat16(x), hy = __float2bfloat16(y);
    __nv_bfloat16 lx = __float2bfloat16(x - __bfloat162float(hx));
    __nv_bfloat16 ly = __float2bfloat16(y - __bfloat162float(hy));
    hp = ((uint32_t)__bfloat16_as_ushort(hy) << 16) | __bfloat16_as_ushort(hx);
    lp = ((uint32_t)__bfloat16_as_ushort(ly) << 16) | __bfloat16_as_ushort(lx);
}

// ===========================================================================
// CSR build (R10 version): zero -> histogram(+slot) -> scan -> reorder
// ===========================================================================
__global__ void zero_cnt() {
    int t = blockIdx.x * blockDim.x + threadIdx.x;
    if (t < NN) g_cnt[t] = 0;
}

__global__ void hist_kernel(const int* __restrict__ dst) {
    int e = blockIdx.x * blockDim.x + threadIdx.x;
    if (e < EE) g_pos[e] = atomicAdd(&g_cnt[__ldg(&dst[e])], 1);
}

constexpr int SCAN_T  = 1024;
constexpr int SCAN_CH = (NN + SCAN_T - 1) / SCAN_T;   // 98

__global__ void scan_kernel() {
    __shared__ int ssum[SCAN_T];
    int t = threadIdx.x;
    int base = t * SCAN_CH;
    int s = 0;
    #pragma unroll 4
    for (int i = 0; i < SCAN_CH; i++) {
        int j = base + i;
        if (j < NN) s += g_cnt[j];
    }
    ssum[t] = s;
    __syncthreads();
    for (int d = 1; d < SCAN_T; d <<= 1) {
        int v = (t >= d) ? ssum[t - d] : 0;
        __syncthreads();
        ssum[t] += v;
        __syncthreads();
    }
    int run = (t > 0) ? ssum[t - 1] : 0;
    for (int i = 0; i < SCAN_CH; i++) {
        int j = base + i;
        if (j < NN) { g_off[j] = run; run += g_cnt[j]; }
    }
}

__global__ void reorder_kernel(const int* __restrict__ src,
                               const int* __restrict__ dst) {
    int e = blockIdx.x * blockDim.x + threadIdx.x;
    if (e < EE) {
        int d = __ldg(&dst[e]);
        g_ssrc[g_off[d] + g_pos[e]] = __ldg(&src[e]);
    }
}

// ===========================================================================
// Gather aggregation -> bf16 hi/lo planes: agg[n] = x[n] + sum_{nbr} x[s]
// ===========================================================================
__global__ void gather_split_64(const float* __restrict__ x) {
    int gw   = (blockIdx.x * blockDim.x + threadIdx.x) >> 5;
    int lane = threadIdx.x & 31;
    int nw   = (gridDim.x * blockDim.x) >> 5;
    for (int n = gw; n < NN; n += nw) {
        int lo = g_off[n], deg = g_cnt[n];
        float2 acc = __ldg((const float2*)(x + (size_t)n * 64) + lane);
        int i = 0;
        for (; i + 3 < deg; i += 4) {
            int s0 = __ldg(&g_ssrc[lo + i]);
            int s1 = __ldg(&g_ssrc[lo + i + 1]);
            int s2 = __ldg(&g_ssrc[lo + i + 2]);
            int s3 = __ldg(&g_ssrc[lo + i + 3]);
            float2 v0 = __ldg((const float2*)(x + (size_t)s0 * 64) + lane);
            float2 v1 = __ldg((const float2*)(x + (size_t)s1 * 64) + lane);
            float2 v2 = __ldg((const float2*)(x + (size_t)s2 * 64) + lane);
            float2 v3 = __ldg((const float2*)(x + (size_t)s3 * 64) + lane);
            acc.x += v0.x + v1.x + v2.x + v3.x;
            acc.y += v0.y + v1.y + v2.y + v3.y;
        }
        for (; i < deg; i++) {
            int s = __ldg(&g_ssrc[lo + i]);
            float2 v = __ldg((const float2*)(x + (size_t)s * 64) + lane);
            acc.x += v.x; acc.y += v.y;
        }
        uint32_t hp, lp;
        split2(acc.x, acc.y, hp, lp);
        g_aggHi[(size_t)n * 32 + lane] = hp;
        g_aggLo[(size_t)n * 32 + lane] = lp;
    }
}

__global__ void gather_split_128(const float* __restrict__ x) {
    int gw   = (blockIdx.x * blockDim.x + threadIdx.x) >> 5;
    int lane = threadIdx.x & 31;
    int nw   = (gridDim.x * blockDim.x) >> 5;
    for (int n = gw; n < NN; n += nw) {
        int lo = g_off[n], deg = g_cnt[n];
        float4 acc = __ldg((const float4*)(x + (size_t)n * 128) + lane);
        int i = 0;
        for (; i + 3 < deg; i += 4) {
            int s0 = __ldg(&g_ssrc[lo + i]);
            int s1 = __ldg(&g_ssrc[lo + i + 1]);
            int s2 = __ldg(&g_ssrc[lo + i + 2]);
            int s3 = __ldg(&g_ssrc[lo + i + 3]);
            float4 v0 = __ldg((const float4*)(x + (size_t)s0 * 128) + lane);
            float4 v1 = __ldg((const float4*)(x + (size_t)s1 * 128) + lane);
            float4 v2 = __ldg((const float4*)(x + (size_t)s2 * 128) + lane);
            float4 v3 = __ldg((const float4*)(x + (size_t)s3 * 128) + lane);
            acc.x += v0.x + v1.x + v2.x + v3.x;
            acc.y += v0.y + v1.y + v2.y + v3.y;
            acc.z += v0.z + v1.z + v2.z + v3.z;
            acc.w += v0.w + v1.w + v2.w + v3.w;
        }
        for (; i < deg; i++) {
            int s = __ldg(&g_ssrc[lo + i]);
            float4 v = __ldg((const float4*)(x + (size_t)s * 128) + lane);
            acc.x += v.x; acc.y += v.y; acc.z += v.z; acc.w += v.w;
        }
        uint2 hp, lp;
        split2(acc.x, acc.y, hp.x, lp.x);
        split2(acc.z, acc.w, hp.y, lp.y);
        *(uint2*)(g_aggHi + (size_t)n * 64 + lane * 2) = hp;
        *(uint2*)(g_aggLo + (size_t)n * 64 + lane * 2) = lp;
    }
}

// ===========================================================================
// Fused GEMM pair (R10 256-thread layout): out = relu(relu(A@W1+b1)@W2+b2)
// POOL=true (layer 2): instead of storing the output, fold mean-pool + FC:
//   per-row p = sum_c relu(acc+b2)[c] * Wfc[c] -> smem row accum -> global
//   atomicAdd into g_gsum[batch[row]].  out is not written at all.
// ===========================================================================
template <int K, bool POOL>
__global__ __launch_bounds__(256, 1)
void fused_pair(const uint32_t* __restrict__ aggHi, const uint32_t* __restrict__ aggLo,
                const float* __restrict__ W1, const float* __restrict__ b1,
                const float* __restrict__ W2, const float* __restrict__ b2,
                float* __restrict__ out,
                const int* __restrict__ batch, const float* __restrict__ Wfc,
                int ntiles)
{
    constexpr int KCH1 = K / 16;         // k-chunks of GEMM1
    constexpr int RSB1 = K * 2 + 16;     // sA row stride bytes (conflict-free)
    constexpr int RSB2 = 128 * 2 + 16;   // sI row stride bytes
    constexpr int KW4  = K / 4;          // uint2 copies per row
    extern __shared__ __align__(16) char smem[];
    char* sAhi = smem;
    char* sAlo = smem + 128 * RSB1;
    char* sIhi = smem + 2 * 128 * RSB1;
    char* sIlo = sIhi + 128 * RSB2;
    __shared__ float sRow[128];

    const int tid  = threadIdx.x;
    const int wid  = tid >> 5;
    const int lane = tid & 31;
    const uint32_t uAhi = smem_u32(sAhi), uAlo = smem_u32(sAlo);
    const uint32_t uIhi = smem_u32(sIhi), uIlo = smem_u32(sIlo);

    // ---- Stage W1^T hi/lo into sI (temp), extract B1 fragments ----
    uint32_t B1hi[KCH1][2][2], B1lo[KCH1][2][2];
    for (int i = tid; i < K * 128; i += 256) {
        int k = i >> 7, n = i & 127;                  // W1[k][n], coalesced
        float w = __ldg(&W1[i]);
        __nv_bfloat16 hi = __float2bfloat16(w);
        __nv_bfloat16 lo = __float2bfloat16(w - __bfloat162float(hi));
        *(__nv_bfloat16*)(sIhi + n * RSB1 + k * 2) = hi;
        *(__nv_bfloat16*)(sIlo + n * RSB1 + k * 2) = lo;
    }
    __syncthreads();
    {
        int r = lane & 7, mat = (lane >> 3) & 1;
        #pragma unroll
        for (int j = 0; j < 2; j++) {
            int n = wid * 16 + j * 8 + r;
            #pragma unroll
            for (int c = 0; c < KCH1; c++) {
                uint32_t off = (uint32_t)n * RSB1 + c * 32 + mat * 16;
                ldmatrix_x2(B1hi[c][j], uIhi + off);
                ldmatrix_x2(B1lo[c][j], uIlo + off);
            }
        }
    }
    __syncthreads();

    // ---- Stage W2^T hi/lo into sI (temp), extract B2 fragments ----
    uint32_t B2hi[8][2][2], B2lo[8][2][2];
    for (int i = tid; i < 128 * 128; i += 256) {
        int k = i >> 7, n = i & 127;
        float w = __ldg(&W2[i]);
        __nv_bfloat16 hi = __float2bfloat16(w);
        __nv_bfloat16 lo = __float2bfloat16(w - __bfloat162float(hi));
        *(__nv_bfloat16*)(sIhi + n * RSB2 + k * 2) = hi;
        *(__nv_bfloat16*)(sIlo + n * RSB2 + k * 2) = lo;
    }
    if (tid < 128) sRow[tid] = 0.f;
    __syncthreads();
    {
        int r = lane & 7, mat = (lane >> 3) & 1;
        #pragma unroll
        for (int j = 0; j < 2; j++) {
            int n = wid * 16 + j * 8 + r;
            #pragma unroll
            for (int c = 0; c < 8; c++) {
                uint32_t off = (uint32_t)n * RSB2 + c * 32 + mat * 16;
                ldmatrix_x2(B2hi[c][j], uIhi + off);
                ldmatrix_x2(B2lo[c][j], uIlo + off);
            }
        }
    }
    __syncthreads();

    // Per-thread bias and Wfc scalars (cols fixed for the whole kernel)
    const int c0 = wid * 16 + (lane & 3) * 2;
    const float b1s00 = __ldg(&b1[c0]),     b1s01 = __ldg(&b1[c0 + 1]);
    const float b1s10 = __ldg(&b1[c0 + 8]), b1s11 = __ldg(&b1[c0 + 9]);
    const float b2s00 = __ldg(&b2[c0]),     b2s01 = __ldg(&b2[c0 + 1]);
    const float b2s10 = __ldg(&b2[c0 + 8]), b2s11 = __ldg(&b2[c0 + 9]);
    float wf00 = 0.f, wf01 = 0.f, wf10 = 0.f, wf11 = 0.f;
    if (POOL) {
        wf00 = __ldg(&Wfc[c0]);     wf01 = __ldg(&Wfc[c0 + 1]);
        wf10 = __ldg(&Wfc[c0 + 8]); wf11 = __ldg(&Wfc[c0 + 9]);
    }

    // ldmatrix.x4 lane address pattern for A (row-major 16x16)
    const int ar = (lane & 7) + ((lane & 8) ? 8 : 0);
    const int ak = (lane & 16) ? 16 : 0;

    for (int tile = blockIdx.x; tile < ntiles; tile += gridDim.x) {
        const int base = tile * 128;

        // ---- 1) Copy pre-split A planes into smem (uint2 = 4 bf16) ----
        for (int i = tid; i < 128 * KW4; i += 256) {
            int row = i / KW4;
            int j   = i - row * KW4;          // uint2 index within row
            int n   = base + row;
            uint2 hp = make_uint2(0u, 0u), lp = make_uint2(0u, 0u);
            if (n < NN) {
                hp = __ldg((const uint2*)(aggHi + (size_t)n * (K / 2)) + j);
                lp = __ldg((const uint2*)(aggLo + (size_t)n * (K / 2)) + j);
            }
            *(uint2*)(sAhi + row * RSB1 + j * 8) = hp;
            *(uint2*)(sAlo + row * RSB1 + j * 8) = lp;
        }
        __syncthreads();

        // ---- 2) GEMM1 (m-tile pairs) -> relu -> split -> sI ----
        #pragma unroll
        for (int mp = 0; mp < 4; mp++) {
            float acc[2][2][4];
            #pragma unroll
            for (int t = 0; t < 2; t++)
                #pragma unroll
                for (int j = 0; j < 2; j++)
                    #pragma unroll
                    for (int q = 0; q < 4; q++) acc[t][j][q] = 0.f;

            #pragma unroll
            for (int c = 0; c < KCH1; c++) {
                #pragma unroll
                for (int t = 0; t < 2; t++) {
                    uint32_t arow = (uint32_t)(mp * 32 + t * 16 + ar) * RSB1 + ak + c * 32;
                    uint32_t ahi[4], alo[4];
                    ldmatrix_x4(ahi, uAhi + arow);
                    ldmatrix_x4(alo, uAlo + arow);
                    #pragma unroll
                    for (int j = 0; j < 2; j++) {
                        mma_16816(acc[t][j], ahi, B1hi[c][j]);
                        mma_16816(acc[t][j], ahi, B1lo[c][j]);
                        mma_16816(acc[t][j], alo, B1hi[c][j]);
                    }
                }
            }
            #pragma unroll
            for (int t = 0; t < 2; t++) {
                int r0 = mp * 32 + t * 16 + (lane >> 2);
                int r1 = r0 + 8;
                #pragma unroll
                for (int j = 0; j < 2; j++) {
                    float bx = j ? b1s10 : b1s00;
                    float by = j ? b1s11 : b1s01;
                    int cc = wid * 16 + j * 8 + (lane & 3) * 2;
                    float v0 = fmaxf(acc[t][j][0] + bx, 0.f);
                    float v1 = fmaxf(acc[t][j][1] + by, 0.f);
                    float v2 = fmaxf(acc[t][j][2] + bx, 0.f);
                    float v3 = fmaxf(acc[t][j][3] + by, 0.f);
                    uint32_t hp, lp;
                    split2(v0, v1, hp, lp);
                    *(uint32_t*)(sIhi + r0 * RSB2 + cc * 2) = hp;
                    *(uint32_t*)(sIlo + r0 * RSB2 + cc * 2) = lp;
                    split2(v2, v3, hp, lp);
                    *(uint32_t*)(sIhi + r1 * RSB2 + cc * 2) = hp;
                    *(uint32_t*)(sIlo + r1 * RSB2 + cc * 2) = lp;
                }
            }
        }
        __syncthreads();

        // ---- 3) GEMM2 (m-tile pairs) -> bias+relu -> gmem or pool ----
        #pragma unroll
        for (int mp = 0; mp < 4; mp++) {
            float acc[2][2][4];
            #pragma unroll
            for (int t = 0; t < 2; t++)
                #pragma unroll
                for (int j = 0; j < 2; j++)
                    #pragma unroll
                    for (int q = 0; q < 4; q++) acc[t][j][q] = 0.f;

            #pragma unroll
            for (int c = 0; c < 8; c++) {
                #pragma unroll
                for (int t = 0; t < 2; t++) {
                    uint32_t arow = (uint32_t)(mp * 32 + t * 16 + ar) * RSB2 + ak + c * 32;
                    uint32_t ahi[4], alo[4];
                    ldmatrix_x4(ahi, uIhi + arow);
                    ldmatrix_x4(alo, uIlo + arow);
                    #pragma unroll
                    for (int j = 0; j < 2; j++) {
                        mma_16816(acc[t][j], ahi, B2hi[c][j]);
                        mma_16816(acc[t][j], ahi, B2lo[c][j]);
                        mma_16816(acc[t][j], alo, B2hi[c][j]);
                    }
                }
            }
            #pragma unroll
            for (int t = 0; t < 2; t++) {
                int rl0 = mp * 32 + t * 16 + (lane >> 2);
                int rl1 = rl0 + 8;
                if (POOL) {
                    float p0 = 0.f, p1 = 0.f;
                    #pragma unroll
                    for (int j = 0; j < 2; j++) {
                        float bx = j ? b2s10 : b2s00;
                        float by = j ? b2s11 : b2s01;
                        float wx = j ? wf10 : wf00;
                        float wy = j ? wf11 : wf01;
                        p0 += fmaxf(acc[t][j][0] + bx, 0.f) * wx
                            + fmaxf(acc[t][j][1] + by, 0.f) * wy;
                        p1 += fmaxf(acc[t][j][2] + bx, 0.f) * wx
                            + fmaxf(acc[t][j][3] + by, 0.f) * wy;
                    }
                    // reduce over the 4 lanes sharing each row (lane&3)
                    p0 += __shfl_xor_sync(0xffffffffu, p0, 1);
                    p0 += __shfl_xor_sync(0xffffffffu, p0, 2);
                    p1 += __shfl_xor_sync(0xffffffffu, p1, 1);
                    p1 += __shfl_xor_sync(0xffffffffu, p1, 2);
                    if ((lane & 3) == 0) {
                        atomicAdd(&sRow[rl0], p0);
                        atomicAdd(&sRow[rl1], p1);
                    }
                } else {
                    int r0 = base + rl0;
                    int r1 = base + rl1;
                    #pragma unroll
                    for (int j = 0; j < 2; j++) {
                        float bx = j ? b2s10 : b2s00;
                        float by = j ? b2s11 : b2s01;
                        int cc = wid * 16 + j * 8 + (lane & 3) * 2;
                        if (r0 < NN) {
                            float2 o;
                            o.x = fmaxf(acc[t][j][0] + bx, 0.f);
                            o.y = fmaxf(acc[t][j][1] + by, 0.f);
                            *(float2*)(out + (size_t)r0 * 128 + cc) = o;
                        }
                        if (r1 < NN) {
                            float2 o;
                            o.x = fmaxf(acc[t][j][2] + bx, 0.f);
                            o.y = fmaxf(acc[t][j][3] + by, 0.f);
                            *(float2*)(out + (size_t)r1 * 128 + cc) = o;
                        }
                    }
                }
            }
        }
        if (POOL) {
            __syncthreads();
            for (int r = tid; r < 128; r += 256) {
                int n = base + r;
                if (n < NN) {
                    float v = sRow[r];
                    atomicAdd(&g_gsum[__ldg(&batch[n])], v);
                }
                sRow[r] = 0.f;
            }
        }
        __syncthreads();   // sA/sI (and sRow) ready before next tile
    }
}

// ===========================================================================
__global__ void zero_pool() {
    int t = threadIdx.x;
    if (t < GG) g_gsum[t] = 0.f;
}

// counts per graph via binary search on the SORTED batch array
__global__ void finalize(const int* __restrict__ batch,
                         float* __restrict__ out, const float* __restrict__ bfc) {
    int g = threadIdx.x;
    if (g >= GG) return;
    int lo = 0, hi = NN;
    while (lo < hi) { int m = (lo + hi) >> 1; if (__ldg(&batch[m]) < g) lo = m + 1; else hi = m; }
    int lb = lo;
    lo = 0; hi = NN;
    while (lo < hi) { int m = (lo + hi) >> 1; if (__ldg(&batch[m]) < g + 1) lo = m + 1; else hi = m; }
    int cnt = lo - lb;
    out[g] = g_gsum[g] / fmaxf((float)cnt, 1.0f) + bfc[0];
}

// ===========================================================================
extern "C" void kernel_launch(void* const* d_in, const int* in_sizes, int n_in,
                              void* d_out, int out_size) {
    const float* x     = (const float*)d_in[0];
    const int*   ei    = (const int*)d_in[1];     // int32
    const int*   batch = (const int*)d_in[2];     // int32 (sorted)
    const float* W1a = (const float*)d_in[3];
    const float* b1a = (const float*)d_in[4];
    const float* W1b = (const float*)d_in[5];
    const float* b1b = (const float*)d_in[6];
    const float* W2a = (const float*)d_in[7];
    const float* b2a = (const float*)d_in[8];
    const float* W2b = (const float*)d_in[9];
    const float* b2b = (const float*)d_in[10];
    const float* Wfc = (const float*)d_in[11];
    const float* bfc = (const float*)d_in[12];
    float* out = (float*)d_out;

    const int* esrc = ei;
    const int* edst = ei + EE;

    float *h1;
    uint32_t *aggHi, *aggLo;
    cudaGetSymbolAddress((void**)&h1, g_h1);
    cudaGetSymbolAddress((void**)&aggHi, g_aggHi);
    cudaGetSymbolAddress((void**)&aggLo, g_aggLo);

    const int smemF64  = 2 * 128 * (64 * 2 + 16) + 2 * 128 * (128 * 2 + 16);   // 106,496
    const int smemF128 = 4 * 128 * (128 * 2 + 16);                             // 139,264
    cudaFuncSetAttribute(fused_pair<64, false>,  cudaFuncAttributeMaxDynamicSharedMemorySize, smemF64);
    cudaFuncSetAttribute(fused_pair<128, true>,  cudaFuncAttributeMaxDynamicSharedMemorySize, smemF128);

    const int ntiles = (NN + 127) / 128;   // 782

    // ---- CSR build (per call; reused by both layers) ----
    zero_cnt<<<(NN + 255) / 256, 256>>>();
    hist_kernel<<<(EE + 255) / 256, 256>>>(edst);
    scan_kernel<<<1, SCAN_T>>>();
    reorder_kernel<<<(EE + 255) / 256, 256>>>(esrc, edst);

    // ---- Layer 1 (writes h1) ----
    gather_split_64<<<1024, 256>>>(x);
    fused_pair<64, false><<<148, 256, smemF64>>>(aggHi, aggLo, W1a, b1a, W1b, b1b,
                                                 h1, nullptr, nullptr, ntiles);

    // ---- Layer 2 (pool fused into epilogue; writes only g_gsum) ----
    zero_pool<<<1, 256>>>();
    gather_split_128<<<1024, 256>>>(h1);
    fused_pair<128, true><<<148, 256, smemF128>>>(aggHi, aggLo, W2a, b2a, W2b, b2b,
                                                  nullptr, batch, Wfc, ntiles);

    // ---- Finalize (counts via binary search on sorted batch) ----
    finalize<<<1, 256>>>(batch, out, bfc);
}